// round 3
// baseline (speedup 1.0000x reference)
#include <cuda_runtime.h>

#define NN 50000
#define CC 64
#define CH2 128
#define EE 800000
#define GEPS 1e-7f
#define BNEPS 1e-5f

__device__ __align__(16) int   g_deg[NN];
__device__ __align__(16) int   g_rowptr[NN + 1];
__device__ __align__(16) int   g_cursor[NN];
__device__ __align__(16) int   g_colidx[EE];
__device__ __align__(16) float g_h0[NN * CC];
__device__ __align__(16) float g_h1[NN * CH2];
__device__ __align__(16) float g_xbuf[NN * CC];
__device__ __align__(16) float g_stats[2 * CH2];
__device__ __align__(16) float g_bn[2 * CH2];   // scale, shift
__device__ int g_is64;

// Detect int64 vs int32 edge_index layout: if int64 (values < 2^31, LE),
// all odd 32-bit words of the first 64 entries are zero.
__global__ void k_detect(const int* __restrict__ w) {
    int any = 0;
#pragma unroll
    for (int i = 1; i < 128; i += 2) any |= w[i];
    g_is64 = (any == 0) ? 1 : 0;
}

__global__ void k_zero_deg() {
    int i = blockIdx.x * blockDim.x + threadIdx.x;
    if (i < NN) g_deg[i] = 0;
}

__global__ void k_zero_stats() {
    int i = threadIdx.x;
    if (i < 2 * CH2) g_stats[i] = 0.f;
}

__global__ void k_hist(const int* __restrict__ w) {
    int e = blockIdx.x * blockDim.x + threadIdx.x;
    if (e < EE) {
        int is64 = g_is64;
        int dstv = is64 ? w[2 * (EE + e)] : w[EE + e];
        atomicAdd(&g_deg[dstv], 1);
    }
}

// single-block exclusive scan of degrees -> rowptr (+ cursor copy)
__global__ void k_scan() {
    __shared__ int s[1024];
    int tid = threadIdx.x;
    int offset = 0;
    for (int base = 0; base < NN; base += 1024) {
        int i = base + tid;
        int v = (i < NN) ? g_deg[i] : 0;
        s[tid] = v;
        __syncthreads();
        for (int d = 1; d < 1024; d <<= 1) {
            int v2 = 0;
            if (tid >= d) v2 = s[tid - d];
            __syncthreads();
            if (tid >= d) s[tid] += v2;
            __syncthreads();
        }
        if (i < NN) {
            int excl = offset + s[tid] - v;
            g_rowptr[i] = excl;
            g_cursor[i] = excl;
        }
        offset += s[1023];
        __syncthreads();
    }
    if (tid == 0) g_rowptr[NN] = offset;
}

__global__ void k_scatter(const int* __restrict__ w) {
    int e = blockIdx.x * blockDim.x + threadIdx.x;
    if (e < EE) {
        int is64 = g_is64;
        int srcv = is64 ? w[2 * e] : w[e];
        int dstv = is64 ? w[2 * (EE + e)] : w[EE + e];
        int p = atomicAdd(&g_cursor[dstv], 1);
        g_colidx[p] = srcv;
    }
}

// warp-per-node softmax aggregation (single edge pass; max-shift cancels exactly)
// g_h0 = segsum(m*exp(m*t)) / (segsum(exp(m*t)) + 1e-16) + x
__global__ void k_aggr(const float* __restrict__ x_in, const float* __restrict__ tp,
                       int layer) {
    int gw = (blockIdx.x * blockDim.x + threadIdx.x) >> 5;
    int lane = threadIdx.x & 31;
    if (gw >= NN) return;
    const float* xp = (layer == 0) ? x_in : g_xbuf;
    float t = __ldg(&tp[layer]);
    int beg = g_rowptr[gw], end = g_rowptr[gw + 1];
    const float2* x2 = (const float2*)xp;
    float den0 = 0.f, den1 = 0.f, num0 = 0.f, num1 = 0.f;
    int i = beg;
    int s = (i < end) ? g_colidx[i] : 0;
    for (; i < end; i++) {
        int snext = (i + 1 < end) ? g_colidx[i + 1] : 0;
        float2 xv = x2[(size_t)s * 32 + lane];
        float m0 = fmaxf(xv.x, 0.f) + GEPS;
        float m1 = fmaxf(xv.y, 0.f) + GEPS;
        float e0 = __expf(m0 * t);
        float e1 = __expf(m1 * t);
        den0 += e0; num0 += m0 * e0;
        den1 += e1; num1 += m1 * e1;
        s = snext;
    }
    float2 xv = x2[(size_t)gw * 32 + lane];
    float2 o;
    o.x = num0 / (den0 + 1e-16f) + xv.x;
    o.y = num1 / (den1 + 1e-16f) + xv.y;
    ((float2*)g_h0)[(size_t)gw * 32 + lane] = o;
}

// GEMM1: g_h1[NN,128] = g_h0[NN,64] @ W[64,128] + b ; fused BN partial stats
// dynamic smem: As 64x64 (16384B) + Bs 64x128 (32768B) = 49152B exactly
__global__ void k_gemm1(const float* __restrict__ W, const float* __restrict__ bias) {
    extern __shared__ float sm[];
    float* As = sm;               // [64][64]
    float* Bs = sm + 64 * 64;     // [64][128]
    int tid = threadIdx.x;
    int m0 = blockIdx.x * 64;

    for (int i = tid; i < 64 * 16; i += 256) {
        int r = i >> 4, c = (i & 15) << 2;
        float4 v = make_float4(0.f, 0.f, 0.f, 0.f);
        if (m0 + r < NN) v = *(const float4*)(g_h0 + (size_t)(m0 + r) * CC + c);
        *(float4*)(As + r * 64 + c) = v;
    }
    for (int i = tid; i < 64 * 32; i += 256)
        ((float4*)Bs)[i] = ((const float4*)W)[i];
    __syncthreads();

    int tx = tid & 15, ty = tid >> 4;
    float acc[4][8];
#pragma unroll
    for (int r = 0; r < 4; r++)
#pragma unroll
        for (int c = 0; c < 8; c++) acc[r][c] = 0.f;

#pragma unroll 8
    for (int k = 0; k < 64; k++) {
        float a0 = As[(ty * 4 + 0) * 64 + k];
        float a1 = As[(ty * 4 + 1) * 64 + k];
        float a2 = As[(ty * 4 + 2) * 64 + k];
        float a3 = As[(ty * 4 + 3) * 64 + k];
#pragma unroll
        for (int c = 0; c < 8; c++) {
            float b = Bs[k * CH2 + tx + c * 16];
            acc[0][c] = fmaf(a0, b, acc[0][c]);
            acc[1][c] = fmaf(a1, b, acc[1][c]);
            acc[2][c] = fmaf(a2, b, acc[2][c]);
            acc[3][c] = fmaf(a3, b, acc[3][c]);
        }
    }
    __syncthreads();   // done reading Bs; reuse as reduction scratch

    float bb[8], ps[8], pq[8];
#pragma unroll
    for (int c = 0; c < 8; c++) { bb[c] = __ldg(&bias[tx + c * 16]); ps[c] = 0.f; pq[c] = 0.f; }
#pragma unroll
    for (int r = 0; r < 4; r++) {
        int row = m0 + ty * 4 + r;
        if (row < NN) {
#pragma unroll
            for (int c = 0; c < 8; c++) {
                float v = acc[r][c] + bb[c];
                g_h1[(size_t)row * CH2 + tx + c * 16] = v;
                ps[c] += v; pq[c] += v * v;
            }
        }
    }
    float* red = Bs;
#pragma unroll
    for (int c = 0; c < 8; c++) {
        red[ty * CH2 + tx + c * 16] = ps[c];
        red[2048 + ty * CH2 + tx + c * 16] = pq[c];
    }
    __syncthreads();
    if (tid < CH2) {
        float s1 = 0.f, s2 = 0.f;
#pragma unroll
        for (int j = 0; j < 16; j++) { s1 += red[j * CH2 + tid]; s2 += red[2048 + j * CH2 + tid]; }
        atomicAdd(&g_stats[tid], s1);
        atomicAdd(&g_stats[CH2 + tid], s2);
    }
}

__global__ void k_bnfinal(const float* __restrict__ gamma, const float* __restrict__ beta) {
    int c = threadIdx.x;
    float inv = 1.f / (float)NN;
    float mean = g_stats[c] * inv;
    float var = g_stats[CH2 + c] * inv - mean * mean;
    float sc = gamma[c] * rsqrtf(var + BNEPS);
    g_bn[c] = sc;
    g_bn[CH2 + c] = beta[c] - mean * sc;
}

// GEMM2: out[NN,64] = relu( relu(BN(g_h1)) @ W[128,64] + b ); BN+ReLU fused into A load
// dynamic smem: As 32x128 (16384B) + Bs 128x64 (32768B) = 49152B exactly
__global__ void k_gemm2(const float* __restrict__ W, const float* __restrict__ bias,
                        float* __restrict__ Oout, int to_out) {
    extern __shared__ float sm[];
    float* As = sm;                // [32][128]
    float* Bs = sm + 32 * CH2;     // [128][64]
    int tid = threadIdx.x;
    int m0 = blockIdx.x * 32;
    float* O = to_out ? Oout : g_xbuf;

    for (int i = tid; i < 32 * 32; i += 256) {
        int r = i >> 5, c = (i & 31) << 2;
        float4 v = make_float4(0.f, 0.f, 0.f, 0.f);
        if (m0 + r < NN) v = *(const float4*)(g_h1 + (size_t)(m0 + r) * CH2 + c);
        float s0 = g_bn[c],     h0v = g_bn[CH2 + c];
        float s1 = g_bn[c + 1], h1v = g_bn[CH2 + c + 1];
        float s2 = g_bn[c + 2], h2v = g_bn[CH2 + c + 2];
        float s3 = g_bn[c + 3], h3v = g_bn[CH2 + c + 3];
        As[r * CH2 + c]     = fmaxf(fmaf(v.x, s0, h0v), 0.f);
        As[r * CH2 + c + 1] = fmaxf(fmaf(v.y, s1, h1v), 0.f);
        As[r * CH2 + c + 2] = fmaxf(fmaf(v.z, s2, h2v), 0.f);
        As[r * CH2 + c + 3] = fmaxf(fmaf(v.w, s3, h3v), 0.f);
    }
    for (int i = tid; i < 128 * 16; i += 256)
        ((float4*)Bs)[i] = ((const float4*)W)[i];
    __syncthreads();

    int tx = tid & 15, ty = tid >> 4;
    float acc[2][4];
#pragma unroll
    for (int r = 0; r < 2; r++)
#pragma unroll
        for (int c = 0; c < 4; c++) acc[r][c] = 0.f;

#pragma unroll 8
    for (int k = 0; k < 128; k++) {
        float a0 = As[(ty * 2 + 0) * CH2 + k];
        float a1 = As[(ty * 2 + 1) * CH2 + k];
#pragma unroll
        for (int c = 0; c < 4; c++) {
            float b = Bs[k * CC + tx + c * 16];
            acc[0][c] = fmaf(a0, b, acc[0][c]);
            acc[1][c] = fmaf(a1, b, acc[1][c]);
        }
    }
#pragma unroll
    for (int r = 0; r < 2; r++) {
        int row = m0 + ty * 2 + r;
        if (row < NN) {
#pragma unroll
            for (int c = 0; c < 4; c++) {
                O[(size_t)row * CC + tx + c * 16] =
                    fmaxf(acc[r][c] + __ldg(&bias[tx + c * 16]), 0.f);
            }
        }
    }
}

extern "C" void kernel_launch(void* const* d_in, const int* in_sizes, int n_in,
                              void* d_out, int out_size) {
    const float* x  = (const float*)d_in[0];
    const int*   ei = (const int*)d_in[1];     // int32 or int64 (auto-detected)
    const float* W1 = (const float*)d_in[2];
    const float* b1 = (const float*)d_in[3];
    const float* gm = (const float*)d_in[4];
    const float* bt = (const float*)d_in[5];
    const float* W2 = (const float*)d_in[6];
    const float* b2 = (const float*)d_in[7];
    const float* tt = (const float*)d_in[8];
    float* out = (float*)d_out;

    const int smem1 = (64 * 64 + 64 * 128) * 4;     // 49152 B (default limit)
    const int smem2 = (32 * 128 + 128 * 64) * 4;    // 49152 B

    // CSR build (recomputed every call; edge_index is an input)
    k_detect<<<1, 1>>>(ei);
    k_zero_deg<<<(NN + 255) / 256, 256>>>();
    k_hist<<<(EE + 255) / 256, 256>>>(ei);
    k_scan<<<1, 1024>>>();
    k_scatter<<<(EE + 255) / 256, 256>>>(ei);

    for (int l = 0; l < 2; l++) {
        k_zero_stats<<<1, 256>>>();
        k_aggr<<<(NN * 32 + 255) / 256, 256>>>(x, tt, l);
        k_gemm1<<<(NN + 63) / 64, 256, smem1>>>(W1 + (size_t)l * CC * CH2, b1 + l * CH2);
        k_bnfinal<<<1, CH2>>>(gm + l * CH2, bt + l * CH2);
        k_gemm2<<<(NN + 31) / 32, 256, smem2>>>(W2 + (size_t)l * CH2 * CC, b2 + l * CC,
                                                out, l == 1);
    }
}

// round 4
// speedup vs baseline: 1.0628x; 1.0628x over previous
#include <cuda_runtime.h>

#define NN 50000
#define CC 64
#define CH2 128
#define EE 800000
#define GEPS 1e-7f
#define BNEPS 1e-5f

__device__ __align__(16) int   g_deg[NN];
__device__ __align__(16) int   g_rowptr[NN + 1];
__device__ __align__(16) int   g_cursor[NN];
__device__ __align__(16) int   g_colidx[EE];
__device__ __align__(16) float g_h0[NN * CC];
__device__ __align__(16) float g_h1[NN * CH2];
__device__ __align__(16) float g_xbuf[NN * CC];
__device__ __align__(16) float g_stats[2 * CH2];
__device__ __align__(16) float g_bn[2 * CH2];   // scale, shift
__device__ int g_is64;

// ---- packed f32x2 helpers (sm_103a FFMA2) ----
__device__ __forceinline__ unsigned long long pk2(float x, float y) {
    unsigned long long r;
    asm("mov.b64 %0, {%1, %2};" : "=l"(r) : "f"(x), "f"(y));
    return r;
}
__device__ __forceinline__ void upk2(unsigned long long v, float& x, float& y) {
    asm("mov.b64 {%0, %1}, %2;" : "=f"(x), "=f"(y) : "l"(v));
}
__device__ __forceinline__ void ffma2(unsigned long long& d, unsigned long long a,
                                      unsigned long long b) {
    asm("fma.rn.f32x2 %0, %1, %2, %3;" : "=l"(d) : "l"(a), "l"(b), "l"(d));
}

// Detect int64 vs int32 edge_index layout: if int64 (values < 2^31, LE),
// all odd 32-bit words of the first 64 entries are zero.
__global__ void k_detect(const int* __restrict__ w) {
    int any = 0;
#pragma unroll
    for (int i = 1; i < 128; i += 2) any |= w[i];
    g_is64 = (any == 0) ? 1 : 0;
}

__global__ void k_zero_deg() {
    int i = blockIdx.x * blockDim.x + threadIdx.x;
    if (i < NN) g_deg[i] = 0;
}

__global__ void k_zero_stats() {
    int i = threadIdx.x;
    if (i < 2 * CH2) g_stats[i] = 0.f;
}

__global__ void k_hist(const int* __restrict__ w) {
    int e = blockIdx.x * blockDim.x + threadIdx.x;
    if (e < EE) {
        int is64 = g_is64;
        int dstv = is64 ? w[2 * (EE + e)] : w[EE + e];
        atomicAdd(&g_deg[dstv], 1);
    }
}

// single-block two-level shuffle scan of degrees -> rowptr (+ cursor copy)
__global__ void k_scan() {
    __shared__ int wsum[32];
    __shared__ int ctot;
    int tid = threadIdx.x, lane = tid & 31, wid = tid >> 5;
    int offset = 0;
    for (int base = 0; base < NN; base += 1024) {
        int i = base + tid;
        int v = (i < NN) ? g_deg[i] : 0;
        int incl = v;
#pragma unroll
        for (int d = 1; d < 32; d <<= 1) {
            int t = __shfl_up_sync(0xffffffffu, incl, d);
            if (lane >= d) incl += t;
        }
        if (lane == 31) wsum[wid] = incl;
        __syncthreads();
        if (wid == 0) {
            int s = wsum[lane];
            int si = s;
#pragma unroll
            for (int d = 1; d < 32; d <<= 1) {
                int t = __shfl_up_sync(0xffffffffu, si, d);
                if (lane >= d) si += t;
            }
            wsum[lane] = si - s;          // exclusive warp base
            if (lane == 31) ctot = si;    // chunk total
        }
        __syncthreads();
        int excl = offset + wsum[wid] + incl - v;
        if (i < NN) { g_rowptr[i] = excl; g_cursor[i] = excl; }
        offset += ctot;
        __syncthreads();
    }
    if (tid == 0) g_rowptr[NN] = offset;
}

__global__ void k_scatter(const int* __restrict__ w) {
    int e = blockIdx.x * blockDim.x + threadIdx.x;
    if (e < EE) {
        int is64 = g_is64;
        int srcv = is64 ? w[2 * e] : w[e];
        int dstv = is64 ? w[2 * (EE + e)] : w[EE + e];
        int p = atomicAdd(&g_cursor[dstv], 1);
        g_colidx[p] = srcv;
    }
}

// warp-per-node softmax aggregation (single edge pass; max-shift cancels exactly)
__global__ void k_aggr(const float* __restrict__ x_in, const float* __restrict__ tp,
                       int layer) {
    int gw = (blockIdx.x * blockDim.x + threadIdx.x) >> 5;
    int lane = threadIdx.x & 31;
    if (gw >= NN) return;
    const float* xp = (layer == 0) ? x_in : g_xbuf;
    float t = __ldg(&tp[layer]);
    int beg = g_rowptr[gw], end = g_rowptr[gw + 1];
    const float2* x2 = (const float2*)xp;
    float den0 = 0.f, den1 = 0.f, num0 = 0.f, num1 = 0.f;
    int i = beg;
    int s = (i < end) ? g_colidx[i] : 0;
    for (; i < end; i++) {
        int snext = (i + 1 < end) ? g_colidx[i + 1] : 0;
        float2 xv = x2[(size_t)s * 32 + lane];
        float m0 = fmaxf(xv.x, 0.f) + GEPS;
        float m1 = fmaxf(xv.y, 0.f) + GEPS;
        float e0 = __expf(m0 * t);
        float e1 = __expf(m1 * t);
        den0 += e0; num0 += m0 * e0;
        den1 += e1; num1 += m1 * e1;
        s = snext;
    }
    float2 xv = x2[(size_t)gw * 32 + lane];
    float2 o;
    o.x = num0 / (den0 + 1e-16f) + xv.x;
    o.y = num1 / (den1 + 1e-16f) + xv.y;
    ((float2*)g_h0)[(size_t)gw * 32 + lane] = o;
}

// GEMM1: g_h1[NN,128] = g_h0[NN,64] @ W[64,128] + b ; fused BN partial stats
// f32x2 inner loop; thread (tx,ty) owns rows ty*4..+3, cols tx*8..+7 (4 pairs)
__global__ void k_gemm1(const float* __restrict__ W, const float* __restrict__ bias) {
    extern __shared__ float sm[];
    float* As = sm;               // [64][64]
    float* Bs = sm + 64 * 64;     // [64][128]
    int tid = threadIdx.x;
    int m0 = blockIdx.x * 64;

    for (int i = tid; i < 64 * 16; i += 256) {
        int r = i >> 4, c = (i & 15) << 2;
        float4 v = make_float4(0.f, 0.f, 0.f, 0.f);
        if (m0 + r < NN) v = *(const float4*)(g_h0 + (size_t)(m0 + r) * CC + c);
        *(float4*)(As + r * 64 + c) = v;
    }
    for (int i = tid; i < 64 * 32; i += 256)
        ((float4*)Bs)[i] = ((const float4*)W)[i];
    __syncthreads();

    int tx = tid & 15, ty = tid >> 4;
    int col0 = tx * 8;
    unsigned long long acc[4][4];
#pragma unroll
    for (int r = 0; r < 4; r++)
#pragma unroll
        for (int p = 0; p < 4; p++) acc[r][p] = 0ull;

#pragma unroll 8
    for (int k = 0; k < 64; k++) {
        unsigned long long ar[4];
#pragma unroll
        for (int r = 0; r < 4; r++) {
            float a = As[(ty * 4 + r) * 64 + k];
            ar[r] = pk2(a, a);
        }
#pragma unroll
        for (int p = 0; p < 4; p++) {
            unsigned long long bv =
                *(const unsigned long long*)(Bs + k * CH2 + col0 + p * 2);
#pragma unroll
            for (int r = 0; r < 4; r++) ffma2(acc[r][p], ar[r], bv);
        }
    }
    __syncthreads();   // done reading Bs; reuse as reduction scratch

    float bb[8], ps[8], pq[8];
#pragma unroll
    for (int j = 0; j < 8; j++) { bb[j] = __ldg(&bias[col0 + j]); ps[j] = 0.f; pq[j] = 0.f; }
#pragma unroll
    for (int r = 0; r < 4; r++) {
        int row = m0 + ty * 4 + r;
        if (row < NN) {
            float vv[8];
#pragma unroll
            for (int p = 0; p < 4; p++) upk2(acc[r][p], vv[2 * p], vv[2 * p + 1]);
#pragma unroll
            for (int j = 0; j < 8; j++) {
                float v = vv[j] + bb[j];
                vv[j] = v;
                ps[j] += v; pq[j] += v * v;
            }
            *(float4*)(g_h1 + (size_t)row * CH2 + col0) = *(float4*)vv;
            *(float4*)(g_h1 + (size_t)row * CH2 + col0 + 4) = *(float4*)(vv + 4);
        }
    }
    float* red = Bs;
#pragma unroll
    for (int j = 0; j < 8; j++) {
        red[ty * CH2 + col0 + j] = ps[j];
        red[2048 + ty * CH2 + col0 + j] = pq[j];
    }
    __syncthreads();
    if (tid < CH2) {
        float s1 = 0.f, s2 = 0.f;
#pragma unroll
        for (int j = 0; j < 16; j++) { s1 += red[j * CH2 + tid]; s2 += red[2048 + j * CH2 + tid]; }
        atomicAdd(&g_stats[tid], s1);
        atomicAdd(&g_stats[CH2 + tid], s2);
    }
}

__global__ void k_bnfinal(const float* __restrict__ gamma, const float* __restrict__ beta) {
    int c = threadIdx.x;
    float inv = 1.f / (float)NN;
    float mean = g_stats[c] * inv;
    float var = g_stats[CH2 + c] * inv - mean * mean;
    float sc = gamma[c] * rsqrtf(var + BNEPS);
    g_bn[c] = sc;
    g_bn[CH2 + c] = beta[c] - mean * sc;
}

// GEMM2: out[NN,64] = relu( relu(BN(g_h1)) @ W[128,64] + b )
// f32x2 inner loop; thread owns rows ty*2..+1, cols tx*4..+3 (2 pairs)
__global__ void k_gemm2(const float* __restrict__ W, const float* __restrict__ bias,
                        float* __restrict__ Oout, int to_out) {
    extern __shared__ float sm[];
    float* As = sm;                // [32][128]
    float* Bs = sm + 32 * CH2;     // [128][64]
    int tid = threadIdx.x;
    int m0 = blockIdx.x * 32;
    float* O = to_out ? Oout : g_xbuf;

    for (int i = tid; i < 32 * 32; i += 256) {
        int r = i >> 5, c = (i & 31) << 2;
        float4 v = make_float4(0.f, 0.f, 0.f, 0.f);
        if (m0 + r < NN) v = *(const float4*)(g_h1 + (size_t)(m0 + r) * CH2 + c);
        float s0 = g_bn[c],     h0v = g_bn[CH2 + c];
        float s1 = g_bn[c + 1], h1v = g_bn[CH2 + c + 1];
        float s2 = g_bn[c + 2], h2v = g_bn[CH2 + c + 2];
        float s3 = g_bn[c + 3], h3v = g_bn[CH2 + c + 3];
        As[r * CH2 + c]     = fmaxf(fmaf(v.x, s0, h0v), 0.f);
        As[r * CH2 + c + 1] = fmaxf(fmaf(v.y, s1, h1v), 0.f);
        As[r * CH2 + c + 2] = fmaxf(fmaf(v.z, s2, h2v), 0.f);
        As[r * CH2 + c + 3] = fmaxf(fmaf(v.w, s3, h3v), 0.f);
    }
    for (int i = tid; i < 128 * 16; i += 256)
        ((float4*)Bs)[i] = ((const float4*)W)[i];
    __syncthreads();

    int tx = tid & 15, ty = tid >> 4;
    int col0 = tx * 4;
    unsigned long long acc[2][2];
    acc[0][0] = acc[0][1] = acc[1][0] = acc[1][1] = 0ull;

#pragma unroll 8
    for (int k = 0; k < 128; k++) {
        float a0 = As[(ty * 2 + 0) * CH2 + k];
        float a1 = As[(ty * 2 + 1) * CH2 + k];
        unsigned long long ar0 = pk2(a0, a0);
        unsigned long long ar1 = pk2(a1, a1);
        unsigned long long b0 = *(const unsigned long long*)(Bs + k * CC + col0);
        unsigned long long b1 = *(const unsigned long long*)(Bs + k * CC + col0 + 2);
        ffma2(acc[0][0], ar0, b0);
        ffma2(acc[0][1], ar0, b1);
        ffma2(acc[1][0], ar1, b0);
        ffma2(acc[1][1], ar1, b1);
    }
#pragma unroll
    for (int r = 0; r < 2; r++) {
        int row = m0 + ty * 2 + r;
        if (row < NN) {
            float vv[4];
            upk2(acc[r][0], vv[0], vv[1]);
            upk2(acc[r][1], vv[2], vv[3]);
#pragma unroll
            for (int j = 0; j < 4; j++)
                vv[j] = fmaxf(vv[j] + __ldg(&bias[col0 + j]), 0.f);
            *(float4*)(O + (size_t)row * CC + col0) = *(float4*)vv;
        }
    }
}

extern "C" void kernel_launch(void* const* d_in, const int* in_sizes, int n_in,
                              void* d_out, int out_size) {
    const float* x  = (const float*)d_in[0];
    const int*   ei = (const int*)d_in[1];     // int32 or int64 (auto-detected)
    const float* W1 = (const float*)d_in[2];
    const float* b1 = (const float*)d_in[3];
    const float* gm = (const float*)d_in[4];
    const float* bt = (const float*)d_in[5];
    const float* W2 = (const float*)d_in[6];
    const float* b2 = (const float*)d_in[7];
    const float* tt = (const float*)d_in[8];
    float* out = (float*)d_out;

    const int smem1 = (64 * 64 + 64 * 128) * 4;     // 49152 B (default limit)
    const int smem2 = (32 * 128 + 128 * 64) * 4;    // 49152 B

    // CSR build (recomputed every call; edge_index is an input)
    k_detect<<<1, 1>>>(ei);
    k_zero_deg<<<(NN + 255) / 256, 256>>>();
    k_hist<<<(EE + 255) / 256, 256>>>(ei);
    k_scan<<<1, 1024>>>();
    k_scatter<<<(EE + 255) / 256, 256>>>(ei);

    for (int l = 0; l < 2; l++) {
        k_zero_stats<<<1, 256>>>();
        k_aggr<<<(NN * 32 + 255) / 256, 256>>>(x, tt, l);
        k_gemm1<<<(NN + 63) / 64, 256, smem1>>>(W1 + (size_t)l * CC * CH2, b1 + l * CH2);
        k_bnfinal<<<1, CH2>>>(gm + l * CH2, bt + l * CH2);
        k_gemm2<<<(NN + 31) / 32, 256, smem2>>>(W2 + (size_t)l * CH2 * CC, b2 + l * CC,
                                                out, l == 1);
    }
}

// round 5
// speedup vs baseline: 1.1978x; 1.1270x over previous
#include <cuda_runtime.h>

#define NN 50000
#define CC 64
#define CH2 128
#define EE 800000
#define NB 49          // ceil(NN/1024)
#define GEPS 1e-7f
#define BNEPS 1e-5f

__device__ __align__(16) int   g_deg[NN];        // zero-init; re-zeroed by k_scanA
__device__ __align__(16) int   g_rowptr[NN + 1];
__device__ __align__(16) int   g_cursor[NN];
__device__ __align__(16) int   g_colidx[EE];
__device__ __align__(16) int   g_blk[NB];
__device__ __align__(16) int   g_blkoff[NB];
__device__ __align__(16) float g_h0[NN * CC];
__device__ __align__(16) float g_h1[NN * CH2];
__device__ __align__(16) float g_xbuf[NN * CC];
__device__ __align__(16) float g_stats[2 * CH2]; // zero-init; re-zeroed by k_bnfinal
__device__ __align__(16) float g_bn[2 * CH2];    // scale, shift
__device__ int g_is64;

// ---- packed f32x2 helpers (sm_103a FFMA2) ----
__device__ __forceinline__ unsigned long long pk2(float x, float y) {
    unsigned long long r;
    asm("mov.b64 %0, {%1, %2};" : "=l"(r) : "f"(x), "f"(y));
    return r;
}
__device__ __forceinline__ void upk2(unsigned long long v, float& x, float& y) {
    asm("mov.b64 {%0, %1}, %2;" : "=f"(x), "=f"(y) : "l"(v));
}
__device__ __forceinline__ void ffma2(unsigned long long& d, unsigned long long a,
                                      unsigned long long b) {
    asm("fma.rn.f32x2 %0, %1, %2, %3;" : "=l"(d) : "l"(a), "l"(b), "l"(d));
}

// Detect int64 vs int32 edge_index layout: if int64 (values < 2^31, LE),
// all odd 32-bit words of the first 64 entries are zero.
__global__ void k_detect(const int* __restrict__ w) {
    int any = 0;
#pragma unroll
    for (int i = 1; i < 128; i += 2) any |= w[i];
    g_is64 = (any == 0) ? 1 : 0;
}

__global__ void k_hist(const int* __restrict__ w) {
    int e = blockIdx.x * blockDim.x + threadIdx.x;
    if (e < EE) {
        int is64 = g_is64;
        int dstv = is64 ? w[2 * (EE + e)] : w[EE + e];
        atomicAdd(&g_deg[dstv], 1);
    }
}

// phase A: per-block scan (+ re-zero g_deg), block totals to g_blk
__global__ void k_scanA() {
    __shared__ int wsum[32];
    int tid = threadIdx.x, lane = tid & 31, wid = tid >> 5;
    int i = blockIdx.x * 1024 + tid;
    int v = (i < NN) ? g_deg[i] : 0;
    if (i < NN) g_deg[i] = 0;
    int incl = v;
#pragma unroll
    for (int d = 1; d < 32; d <<= 1) {
        int t = __shfl_up_sync(0xffffffffu, incl, d);
        if (lane >= d) incl += t;
    }
    if (lane == 31) wsum[wid] = incl;
    __syncthreads();
    if (wid == 0) {
        int s = wsum[lane];
        int si = s;
#pragma unroll
        for (int d = 1; d < 32; d <<= 1) {
            int t = __shfl_up_sync(0xffffffffu, si, d);
            if (lane >= d) si += t;
        }
        wsum[lane] = si - s;
        if (lane == 31) g_blk[blockIdx.x] = si;
    }
    __syncthreads();
    if (i < NN) g_rowptr[i] = wsum[wid] + incl - v;
}

// phase B: scan NB=49 block totals with one warp
__global__ void k_scanB() {
    int lane = threadIdx.x;
    int a = (lane < NB) ? g_blk[lane] : 0;
    int b = (lane + 32 < NB) ? g_blk[lane + 32] : 0;
    int sa = a, sb = b;
#pragma unroll
    for (int d = 1; d < 32; d <<= 1) {
        int t = __shfl_up_sync(0xffffffffu, sa, d);
        if (lane >= d) sa += t;
        int u = __shfl_up_sync(0xffffffffu, sb, d);
        if (lane >= d) sb += u;
    }
    int T1 = __shfl_sync(0xffffffffu, sa, 31);
    if (lane < NB) g_blkoff[lane] = sa - a;
    if (lane + 32 < NB) g_blkoff[lane + 32] = T1 + sb - b;
}

// phase C: add block offsets, copy cursor, terminal rowptr
__global__ void k_scanC() {
    int i = blockIdx.x * 1024 + threadIdx.x;
    if (i < NN) {
        int r = g_rowptr[i] + g_blkoff[blockIdx.x];
        g_rowptr[i] = r;
        g_cursor[i] = r;
    }
    if (i == 0) g_rowptr[NN] = EE;
}

__global__ void k_scatter(const int* __restrict__ w) {
    int e = blockIdx.x * blockDim.x + threadIdx.x;
    if (e < EE) {
        int is64 = g_is64;
        int srcv = is64 ? w[2 * e] : w[e];
        int dstv = is64 ? w[2 * (EE + e)] : w[EE + e];
        int p = atomicAdd(&g_cursor[dstv], 1);
        g_colidx[p] = srcv;
    }
}

// warp-per-node softmax aggregation (single edge pass; max-shift cancels exactly)
__global__ void k_aggr(const float* __restrict__ x_in, const float* __restrict__ tp,
                       int layer) {
    int gw = (blockIdx.x * blockDim.x + threadIdx.x) >> 5;
    int lane = threadIdx.x & 31;
    if (gw >= NN) return;
    const float* xp = (layer == 0) ? x_in : g_xbuf;
    float t = __ldg(&tp[layer]);
    int beg = g_rowptr[gw], end = g_rowptr[gw + 1];
    const float2* x2 = (const float2*)xp;
    float den0 = 0.f, den1 = 0.f, num0 = 0.f, num1 = 0.f;
    int i = beg;
    int s = (i < end) ? g_colidx[i] : 0;
    for (; i < end; i++) {
        int snext = (i + 1 < end) ? g_colidx[i + 1] : 0;
        float2 xv = x2[(size_t)s * 32 + lane];
        float m0 = fmaxf(xv.x, 0.f) + GEPS;
        float m1 = fmaxf(xv.y, 0.f) + GEPS;
        float e0 = __expf(m0 * t);
        float e1 = __expf(m1 * t);
        den0 += e0; num0 += m0 * e0;
        den1 += e1; num1 += m1 * e1;
        s = snext;
    }
    float2 xv = x2[(size_t)gw * 32 + lane];
    float2 o;
    o.x = num0 / (den0 + 1e-16f) + xv.x;
    o.y = num1 / (den1 + 1e-16f) + xv.y;
    ((float2*)g_h0)[(size_t)gw * 32 + lane] = o;
}

// GEMM1: g_h1[NN,128] = g_h0[NN,64] @ W[64,128] + b ; fused BN partial stats
__global__ void k_gemm1(const float* __restrict__ W, const float* __restrict__ bias) {
    extern __shared__ float sm[];
    float* As = sm;               // [64][64]
    float* Bs = sm + 64 * 64;     // [64][128]
    int tid = threadIdx.x;
    int m0 = blockIdx.x * 64;

    for (int i = tid; i < 64 * 16; i += 256) {
        int r = i >> 4, c = (i & 15) << 2;
        float4 v = make_float4(0.f, 0.f, 0.f, 0.f);
        if (m0 + r < NN) v = *(const float4*)(g_h0 + (size_t)(m0 + r) * CC + c);
        *(float4*)(As + r * 64 + c) = v;
    }
    for (int i = tid; i < 64 * 32; i += 256)
        ((float4*)Bs)[i] = ((const float4*)W)[i];
    __syncthreads();

    int tx = tid & 15, ty = tid >> 4;
    int col0 = tx * 8;
    unsigned long long acc[4][4];
#pragma unroll
    for (int r = 0; r < 4; r++)
#pragma unroll
        for (int p = 0; p < 4; p++) acc[r][p] = 0ull;

#pragma unroll 8
    for (int k = 0; k < 64; k++) {
        unsigned long long ar[4];
#pragma unroll
        for (int r = 0; r < 4; r++) {
            float a = As[(ty * 4 + r) * 64 + k];
            ar[r] = pk2(a, a);
        }
#pragma unroll
        for (int p = 0; p < 4; p++) {
            unsigned long long bv =
                *(const unsigned long long*)(Bs + k * CH2 + col0 + p * 2);
#pragma unroll
            for (int r = 0; r < 4; r++) ffma2(acc[r][p], ar[r], bv);
        }
    }
    __syncthreads();   // done reading Bs; reuse as reduction scratch

    float bb[8], ps[8], pq[8];
#pragma unroll
    for (int j = 0; j < 8; j++) { bb[j] = __ldg(&bias[col0 + j]); ps[j] = 0.f; pq[j] = 0.f; }
#pragma unroll
    for (int r = 0; r < 4; r++) {
        int row = m0 + ty * 4 + r;
        if (row < NN) {
            float vv[8];
#pragma unroll
            for (int p = 0; p < 4; p++) upk2(acc[r][p], vv[2 * p], vv[2 * p + 1]);
#pragma unroll
            for (int j = 0; j < 8; j++) {
                float v = vv[j] + bb[j];
                vv[j] = v;
                ps[j] += v; pq[j] += v * v;
            }
            *(float4*)(g_h1 + (size_t)row * CH2 + col0) = *(float4*)vv;
            *(float4*)(g_h1 + (size_t)row * CH2 + col0 + 4) = *(float4*)(vv + 4);
        }
    }
    float* red = Bs;
#pragma unroll
    for (int j = 0; j < 8; j++) {
        red[ty * CH2 + col0 + j] = ps[j];
        red[2048 + ty * CH2 + col0 + j] = pq[j];
    }
    __syncthreads();
    if (tid < CH2) {
        float s1 = 0.f, s2 = 0.f;
#pragma unroll
        for (int j = 0; j < 16; j++) { s1 += red[j * CH2 + tid]; s2 += red[2048 + j * CH2 + tid]; }
        atomicAdd(&g_stats[tid], s1);
        atomicAdd(&g_stats[CH2 + tid], s2);
    }
}

// finalize BN affine; reset g_stats for next layer/call (keeps zero invariant)
__global__ void k_bnfinal(const float* __restrict__ gamma, const float* __restrict__ beta) {
    int c = threadIdx.x;
    float inv = 1.f / (float)NN;
    float mean = g_stats[c] * inv;
    float var = g_stats[CH2 + c] * inv - mean * mean;
    float sc = gamma[c] * rsqrtf(var + BNEPS);
    g_bn[c] = sc;
    g_bn[CH2 + c] = beta[c] - mean * sc;
    g_stats[c] = 0.f;
    g_stats[CH2 + c] = 0.f;
}

// GEMM2: out[NN,64] = relu( relu(BN(g_h1)) @ W[128,64] + b )
__global__ void k_gemm2(const float* __restrict__ W, const float* __restrict__ bias,
                        float* __restrict__ Oout, int to_out) {
    extern __shared__ float sm[];
    float* As = sm;                // [32][128]
    float* Bs = sm + 32 * CH2;     // [128][64]
    int tid = threadIdx.x;
    int m0 = blockIdx.x * 32;
    float* O = to_out ? Oout : g_xbuf;

    for (int i = tid; i < 32 * 32; i += 256) {
        int r = i >> 5, c = (i & 31) << 2;
        float4 v = make_float4(0.f, 0.f, 0.f, 0.f);
        if (m0 + r < NN) v = *(const float4*)(g_h1 + (size_t)(m0 + r) * CH2 + c);
        float s0 = g_bn[c],     h0v = g_bn[CH2 + c];
        float s1 = g_bn[c + 1], h1v = g_bn[CH2 + c + 1];
        float s2 = g_bn[c + 2], h2v = g_bn[CH2 + c + 2];
        float s3 = g_bn[c + 3], h3v = g_bn[CH2 + c + 3];
        As[r * CH2 + c]     = fmaxf(fmaf(v.x, s0, h0v), 0.f);
        As[r * CH2 + c + 1] = fmaxf(fmaf(v.y, s1, h1v), 0.f);
        As[r * CH2 + c + 2] = fmaxf(fmaf(v.z, s2, h2v), 0.f);
        As[r * CH2 + c + 3] = fmaxf(fmaf(v.w, s3, h3v), 0.f);
    }
    for (int i = tid; i < 128 * 16; i += 256)
        ((float4*)Bs)[i] = ((const float4*)W)[i];
    __syncthreads();

    int tx = tid & 15, ty = tid >> 4;
    int col0 = tx * 4;
    unsigned long long acc[2][2];
    acc[0][0] = acc[0][1] = acc[1][0] = acc[1][1] = 0ull;

#pragma unroll 8
    for (int k = 0; k < 128; k++) {
        float a0 = As[(ty * 2 + 0) * CH2 + k];
        float a1 = As[(ty * 2 + 1) * CH2 + k];
        unsigned long long ar0 = pk2(a0, a0);
        unsigned long long ar1 = pk2(a1, a1);
        unsigned long long b0 = *(const unsigned long long*)(Bs + k * CC + col0);
        unsigned long long b1 = *(const unsigned long long*)(Bs + k * CC + col0 + 2);
        ffma2(acc[0][0], ar0, b0);
        ffma2(acc[0][1], ar0, b1);
        ffma2(acc[1][0], ar1, b0);
        ffma2(acc[1][1], ar1, b1);
    }
#pragma unroll
    for (int r = 0; r < 2; r++) {
        int row = m0 + ty * 2 + r;
        if (row < NN) {
            float vv[4];
            upk2(acc[r][0], vv[0], vv[1]);
            upk2(acc[r][1], vv[2], vv[3]);
#pragma unroll
            for (int j = 0; j < 4; j++)
                vv[j] = fmaxf(vv[j] + __ldg(&bias[col0 + j]), 0.f);
            *(float4*)(O + (size_t)row * CC + col0) = *(float4*)vv;
        }
    }
}

extern "C" void kernel_launch(void* const* d_in, const int* in_sizes, int n_in,
                              void* d_out, int out_size) {
    const float* x  = (const float*)d_in[0];
    const int*   ei = (const int*)d_in[1];     // int32 or int64 (auto-detected)
    const float* W1 = (const float*)d_in[2];
    const float* b1 = (const float*)d_in[3];
    const float* gm = (const float*)d_in[4];
    const float* bt = (const float*)d_in[5];
    const float* W2 = (const float*)d_in[6];
    const float* b2 = (const float*)d_in[7];
    const float* tt = (const float*)d_in[8];
    float* out = (float*)d_out;

    const int smem1 = (64 * 64 + 64 * 128) * 4;     // 49152 B (default limit)
    const int smem2 = (32 * 128 + 128 * 64) * 4;    // 49152 B

    // CSR build (recomputed every call; edge_index is an input)
    k_detect<<<1, 1>>>(ei);
    k_hist<<<(EE + 255) / 256, 256>>>(ei);
    k_scanA<<<NB, 1024>>>();
    k_scanB<<<1, 32>>>();
    k_scanC<<<NB, 1024>>>();
    k_scatter<<<(EE + 255) / 256, 256>>>(ei);

    for (int l = 0; l < 2; l++) {
        k_aggr<<<(NN * 32 + 255) / 256, 256>>>(x, tt, l);
        k_gemm1<<<(NN + 63) / 64, 256, smem1>>>(W1 + (size_t)l * CC * CH2, b1 + l * CH2);
        k_bnfinal<<<1, CH2>>>(gm + l * CH2, bt + l * CH2);
        k_gemm2<<<(NN + 31) / 32, 256, smem2>>>(W2 + (size_t)l * CH2 * CC, b2 + l * CC,
                                                out, l == 1);
    }
}

// round 7
// speedup vs baseline: 1.2686x; 1.0591x over previous
#include <cuda_runtime.h>

#define NN 50000
#define CC 64
#define CH2 128
#define EE 800000
#define NB 49          // ceil(NN/1024)
#define GEPS 1e-7f
#define BNEPS 1e-5f

__device__ __align__(16) int   g_deg[NN];        // zero-init; re-zeroed by k_scanA
__device__ __align__(16) int   g_rowptr[NN + 1]; // block-local exclusive prefixes
__device__ __align__(16) int   g_cursor[NN];     // block-local (scatter adds blkoff)
__device__ __align__(16) int   g_colidx[EE];
__device__ __align__(16) int   g_blk[NB];
__device__ __align__(16) int   g_blkoff[NB];
__device__ __align__(16) float g_h0[NN * CC];
__device__ __align__(16) float g_h1[NN * CH2];
__device__ __align__(16) float g_xbuf[NN * CC];
__device__ __align__(16) float g_stats[2 * CH2]; // zero-init; re-zeroed by k_aggr blk0

// ---- packed f32x2 helpers (sm_103a FFMA2) ----
__device__ __forceinline__ unsigned long long pk2(float x, float y) {
    unsigned long long r;
    asm("mov.b64 %0, {%1, %2};" : "=l"(r) : "f"(x), "f"(y));
    return r;
}
__device__ __forceinline__ void upk2(unsigned long long v, float& x, float& y) {
    asm("mov.b64 {%0, %1}, %2;" : "=f"(x), "=f"(y) : "l"(v));
}
__device__ __forceinline__ void ffma2(unsigned long long& d, unsigned long long a,
                                      unsigned long long b) {
    asm("fma.rn.f32x2 %0, %1, %2, %3;" : "=l"(d) : "l"(a), "l"(b), "l"(d));
}

// int64-vs-int32 edge layout probe: int64 (values < 2^31, LE) => odd words zero
__device__ __forceinline__ int detect64(const int* __restrict__ w) {
    int any = 0;
#pragma unroll
    for (int i = 1; i < 128; i += 2) any |= w[i];
    return any == 0;
}

__global__ void k_hist(const int* __restrict__ w) {
    __shared__ int s64;
    if (threadIdx.x == 0) s64 = detect64(w);
    __syncthreads();
    int e = blockIdx.x * blockDim.x + threadIdx.x;
    if (e < EE) {
        int dstv = s64 ? w[2 * (EE + e)] : w[EE + e];
        atomicAdd(&g_deg[dstv], 1);
    }
}

// phase A: per-block scan (+ re-zero g_deg); block totals; local rowptr/cursor
__global__ void k_scanA() {
    __shared__ int wsum[32];
    int tid = threadIdx.x, lane = tid & 31, wid = tid >> 5;
    int i = blockIdx.x * 1024 + tid;
    int v = (i < NN) ? g_deg[i] : 0;
    if (i < NN) g_deg[i] = 0;
    int incl = v;
#pragma unroll
    for (int d = 1; d < 32; d <<= 1) {
        int t = __shfl_up_sync(0xffffffffu, incl, d);
        if (lane >= d) incl += t;
    }
    if (lane == 31) wsum[wid] = incl;
    __syncthreads();
    if (wid == 0) {
        int s = wsum[lane];
        int si = s;
#pragma unroll
        for (int d = 1; d < 32; d <<= 1) {
            int t = __shfl_up_sync(0xffffffffu, si, d);
            if (lane >= d) si += t;
        }
        wsum[lane] = si - s;
        if (lane == 31) g_blk[blockIdx.x] = si;
    }
    __syncthreads();
    if (i < NN) {
        int excl = wsum[wid] + incl - v;
        g_rowptr[i] = excl;
        g_cursor[i] = excl;
        if (i == NN - 1) g_rowptr[NN] = excl + v;   // local total of last block
    }
}

// phase B: scan NB=49 block totals with one warp -> g_blkoff
__global__ void k_scanB() {
    int lane = threadIdx.x;
    int a = (lane < NB) ? g_blk[lane] : 0;
    int b = (lane + 32 < NB) ? g_blk[lane + 32] : 0;
    int sa = a, sb = b;
#pragma unroll
    for (int d = 1; d < 32; d <<= 1) {
        int t = __shfl_up_sync(0xffffffffu, sa, d);
        if (lane >= d) sa += t;
        int u = __shfl_up_sync(0xffffffffu, sb, d);
        if (lane >= d) sb += u;
    }
    int T1 = __shfl_sync(0xffffffffu, sa, 31);
    if (lane < NB) g_blkoff[lane] = sa - a;
    if (lane + 32 < NB) g_blkoff[lane + 32] = T1 + sb - b;
}

__global__ void k_scatter(const int* __restrict__ w) {
    __shared__ int s64;
    if (threadIdx.x == 0) s64 = detect64(w);
    __syncthreads();
    int e = blockIdx.x * blockDim.x + threadIdx.x;
    if (e < EE) {
        int srcv = s64 ? w[2 * e] : w[e];
        int dstv = s64 ? w[2 * (EE + e)] : w[EE + e];
        int p = atomicAdd(&g_cursor[dstv], 1) + g_blkoff[dstv >> 10];
        g_colidx[p] = srcv;
    }
}

// warp-per-node softmax aggregation (single edge pass; max-shift cancels exactly)
// also: block 0 resets g_stats for this layer's gemm1 accumulation
__global__ void k_aggr(const float* __restrict__ x_in, const float* __restrict__ tp,
                       int layer) {
    if (blockIdx.x == 0 && threadIdx.x < 2 * CH2) g_stats[threadIdx.x] = 0.f;
    int gw = (blockIdx.x * blockDim.x + threadIdx.x) >> 5;
    int lane = threadIdx.x & 31;
    if (gw >= NN) return;
    const float* xp = (layer == 0) ? x_in : g_xbuf;
    float t = __ldg(&tp[layer]);
    int beg = g_rowptr[gw] + g_blkoff[gw >> 10];
    int end = g_rowptr[gw + 1] + g_blkoff[(gw + 1) >> 10];
    const float2* x2 = (const float2*)xp;
    float den0 = 0.f, den1 = 0.f, num0 = 0.f, num1 = 0.f;
    int i = beg;
    int s = (i < end) ? g_colidx[i] : 0;
    for (; i < end; i++) {
        int snext = (i + 1 < end) ? g_colidx[i + 1] : 0;
        float2 xv = x2[(size_t)s * 32 + lane];
        float m0 = fmaxf(xv.x, 0.f) + GEPS;
        float m1 = fmaxf(xv.y, 0.f) + GEPS;
        float e0 = __expf(m0 * t);
        float e1 = __expf(m1 * t);
        den0 += e0; num0 += m0 * e0;
        den1 += e1; num1 += m1 * e1;
        s = snext;
    }
    float2 xv = x2[(size_t)gw * 32 + lane];
    float2 o;
    o.x = num0 / (den0 + 1e-16f) + xv.x;
    o.y = num1 / (den1 + 1e-16f) + xv.y;
    ((float2*)g_h0)[(size_t)gw * 32 + lane] = o;
}

// GEMM1: g_h1[NN,128] = g_h0[NN,64] @ W[64,128] + b ; fused BN partial stats
// A stored transposed [k][row] (conflict-free LDS.128); B cols tx*2+p*32 (conflict-free)
__global__ void k_gemm1(const float* __restrict__ W, const float* __restrict__ bias) {
    extern __shared__ float sm[];
    float* As = sm;               // [64k][64row]
    float* Bs = sm + 64 * 64;     // [64][128]
    int tid = threadIdx.x;
    int m0 = blockIdx.x * 64;

    // fill A transposed: lanes take consecutive rows -> conflict-free STS
    for (int i = tid; i < 64 * 16; i += 256) {
        int r = i & 63, cg = i >> 6;           // row, k-group
        float4 v = make_float4(0.f, 0.f, 0.f, 0.f);
        if (m0 + r < NN) v = *(const float4*)(g_h0 + (size_t)(m0 + r) * CC + cg * 4);
        As[(cg * 4 + 0) * 64 + r] = v.x;
        As[(cg * 4 + 1) * 64 + r] = v.y;
        As[(cg * 4 + 2) * 64 + r] = v.z;
        As[(cg * 4 + 3) * 64 + r] = v.w;
    }
    for (int i = tid; i < 64 * 32; i += 256)
        ((float4*)Bs)[i] = ((const float4*)W)[i];
    __syncthreads();

    int tx = tid & 15, ty = tid >> 4;
    unsigned long long acc[4][4];
#pragma unroll
    for (int r = 0; r < 4; r++)
#pragma unroll
        for (int p = 0; p < 4; p++) acc[r][p] = 0ull;

#pragma unroll 8
    for (int k = 0; k < 64; k++) {
        float4 av = *(const float4*)(As + k * 64 + ty * 4);
        unsigned long long ar[4];
        ar[0] = pk2(av.x, av.x);
        ar[1] = pk2(av.y, av.y);
        ar[2] = pk2(av.z, av.z);
        ar[3] = pk2(av.w, av.w);
#pragma unroll
        for (int p = 0; p < 4; p++) {
            unsigned long long bv =
                *(const unsigned long long*)(Bs + k * CH2 + tx * 2 + p * 32);
#pragma unroll
            for (int r = 0; r < 4; r++) ffma2(acc[r][p], ar[r], bv);
        }
    }
    __syncthreads();   // done reading Bs; reuse as reduction scratch

    float bb[8], ps[8], pq[8];
#pragma unroll
    for (int p = 0; p < 4; p++) {
        int col = tx * 2 + p * 32;
        bb[2 * p] = __ldg(&bias[col]); bb[2 * p + 1] = __ldg(&bias[col + 1]);
        ps[2 * p] = ps[2 * p + 1] = 0.f;
        pq[2 * p] = pq[2 * p + 1] = 0.f;
    }
#pragma unroll
    for (int r = 0; r < 4; r++) {
        int row = m0 + ty * 4 + r;
        if (row < NN) {
#pragma unroll
            for (int p = 0; p < 4; p++) {
                float v0, v1;
                upk2(acc[r][p], v0, v1);
                v0 += bb[2 * p]; v1 += bb[2 * p + 1];
                int col = tx * 2 + p * 32;
                *(float2*)(g_h1 + (size_t)row * CH2 + col) = make_float2(v0, v1);
                ps[2 * p] += v0; pq[2 * p] += v0 * v0;
                ps[2 * p + 1] += v1; pq[2 * p + 1] += v1 * v1;
            }
        }
    }
    float* red = Bs;
#pragma unroll
    for (int p = 0; p < 4; p++) {
        int col = tx * 2 + p * 32;
        red[ty * CH2 + col] = ps[2 * p];
        red[ty * CH2 + col + 1] = ps[2 * p + 1];
        red[2048 + ty * CH2 + col] = pq[2 * p];
        red[2048 + ty * CH2 + col + 1] = pq[2 * p + 1];
    }
    __syncthreads();
    if (tid < CH2) {
        float s1 = 0.f, s2 = 0.f;
#pragma unroll
        for (int j = 0; j < 16; j++) { s1 += red[j * CH2 + tid]; s2 += red[2048 + j * CH2 + tid]; }
        atomicAdd(&g_stats[tid], s1);
        atomicAdd(&g_stats[CH2 + tid], s2);
    }
}

// GEMM2: out[NN,64] = relu( relu(BN(g_h1)) @ W[128,64] + b )
// BN affine computed inline during A fill (no static smem!); A transposed [k][row]
__global__ void k_gemm2(const float* __restrict__ W, const float* __restrict__ bias,
                        const float* __restrict__ gamma, const float* __restrict__ beta,
                        float* __restrict__ Oout, int to_out) {
    extern __shared__ float sm[];
    float* As = sm;                // [128k][32row]
    float* Bs = sm + CH2 * 32;     // [128][64]
    int tid = threadIdx.x;
    int m0 = blockIdx.x * 32;
    float* O = to_out ? Oout : g_xbuf;

    for (int i = tid; i < 128 * 16; i += 256)
        ((float4*)Bs)[i] = ((const float4*)W)[i];

    // fill A transposed with BN+ReLU; BN affine derived inline from g_stats
    const float inv = 1.f / (float)NN;
    for (int i = tid; i < 32 * 32; i += 256) {
        int r = i & 31, cg = i >> 5;
        int c = cg * 4;
        float4 v = make_float4(0.f, 0.f, 0.f, 0.f);
        if (m0 + r < NN) v = *(const float4*)(g_h1 + (size_t)(m0 + r) * CH2 + c);
        float4 s1 = *(const float4*)(g_stats + c);
        float4 s2 = *(const float4*)(g_stats + CH2 + c);
        float4 gg = *(const float4*)(gamma + c);
        float4 bb = *(const float4*)(beta + c);
        float m, sc;
        m = s1.x * inv; sc = gg.x * rsqrtf(s2.x * inv - m * m + BNEPS);
        As[(c + 0) * 32 + r] = fmaxf(fmaf(v.x, sc, bb.x - m * sc), 0.f);
        m = s1.y * inv; sc = gg.y * rsqrtf(s2.y * inv - m * m + BNEPS);
        As[(c + 1) * 32 + r] = fmaxf(fmaf(v.y, sc, bb.y - m * sc), 0.f);
        m = s1.z * inv; sc = gg.z * rsqrtf(s2.z * inv - m * m + BNEPS);
        As[(c + 2) * 32 + r] = fmaxf(fmaf(v.z, sc, bb.z - m * sc), 0.f);
        m = s1.w * inv; sc = gg.w * rsqrtf(s2.w * inv - m * m + BNEPS);
        As[(c + 3) * 32 + r] = fmaxf(fmaf(v.w, sc, bb.w - m * sc), 0.f);
    }
    __syncthreads();

    int tx = tid & 15, ty = tid >> 4;
    unsigned long long acc[2][2];
    acc[0][0] = acc[0][1] = acc[1][0] = acc[1][1] = 0ull;

#pragma unroll 8
    for (int k = 0; k < 128; k++) {
        float a0, a1;
        unsigned long long apair = *(const unsigned long long*)(As + k * 32 + ty * 2);
        upk2(apair, a0, a1);
        unsigned long long ar0 = pk2(a0, a0);
        unsigned long long ar1 = pk2(a1, a1);
        unsigned long long b0 = *(const unsigned long long*)(Bs + k * CC + tx * 2);
        unsigned long long b1 = *(const unsigned long long*)(Bs + k * CC + tx * 2 + 32);
        ffma2(acc[0][0], ar0, b0);
        ffma2(acc[0][1], ar0, b1);
        ffma2(acc[1][0], ar1, b0);
        ffma2(acc[1][1], ar1, b1);
    }
#pragma unroll
    for (int r = 0; r < 2; r++) {
        int row = m0 + ty * 2 + r;
        if (row < NN) {
#pragma unroll
            for (int p = 0; p < 2; p++) {
                int col = tx * 2 + p * 32;
                float v0, v1;
                upk2(acc[r][p], v0, v1);
                v0 = fmaxf(v0 + __ldg(&bias[col]), 0.f);
                v1 = fmaxf(v1 + __ldg(&bias[col + 1]), 0.f);
                *(float2*)(O + (size_t)row * CC + col) = make_float2(v0, v1);
            }
        }
    }
}

extern "C" void kernel_launch(void* const* d_in, const int* in_sizes, int n_in,
                              void* d_out, int out_size) {
    const float* x  = (const float*)d_in[0];
    const int*   ei = (const int*)d_in[1];     // int32 or int64 (auto-detected)
    const float* W1 = (const float*)d_in[2];
    const float* b1 = (const float*)d_in[3];
    const float* gm = (const float*)d_in[4];
    const float* bt = (const float*)d_in[5];
    const float* W2 = (const float*)d_in[6];
    const float* b2 = (const float*)d_in[7];
    const float* tt = (const float*)d_in[8];
    float* out = (float*)d_out;

    const int smem1 = (64 * 64 + 64 * 128) * 4;     // 49152 B, zero static
    const int smem2 = (128 * 32 + 128 * 64) * 4;    // 49152 B, zero static

    // CSR build (recomputed every call; edge_index is an input)
    k_hist<<<(EE + 255) / 256, 256>>>(ei);
    k_scanA<<<NB, 1024>>>();
    k_scanB<<<1, 32>>>();
    k_scatter<<<(EE + 255) / 256, 256>>>(ei);

    for (int l = 0; l < 2; l++) {
        k_aggr<<<(NN * 32 + 255) / 256, 256>>>(x, tt, l);
        k_gemm1<<<(NN + 63) / 64, 256, smem1>>>(W1 + (size_t)l * CC * CH2, b1 + l * CH2);
        k_gemm2<<<(NN + 31) / 32, 256, smem2>>>(W2 + (size_t)l * CH2 * CC, b2 + l * CC,
                                                gm + l * CH2, bt + l * CH2, out, l == 1);
    }
}

// round 8
// speedup vs baseline: 1.3391x; 1.0556x over previous
#include <cuda_runtime.h>

#define NN 50000
#define CC 64
#define CH2 128
#define EE 800000
#define NB 49          // ceil(NN/1024)
#define GEPS 1e-7f
#define BNEPS 1e-5f

__device__ __align__(16) int   g_deg[NN];        // zero-init; re-zeroed by k_scanA
__device__ __align__(16) int   g_rowptr[NN + 1]; // block-local exclusive prefixes
__device__ __align__(16) int   g_cursor[NN];     // block-local (scatter adds blkoff)
__device__ __align__(16) int   g_colidx[EE];
__device__ __align__(16) int   g_blk[NB];
__device__ __align__(16) int   g_blkoff[NB];
__device__ __align__(16) float g_h1[NN * CH2];
__device__ __align__(16) float g_xbuf[NN * CC];
__device__ __align__(16) float g_stats[2 * 2 * CH2]; // per-layer [2][256]; zeroed by k_scanB

// ---- packed f32x2 helpers (sm_103a FFMA2) ----
__device__ __forceinline__ unsigned long long pk2(float x, float y) {
    unsigned long long r;
    asm("mov.b64 %0, {%1, %2};" : "=l"(r) : "f"(x), "f"(y));
    return r;
}
__device__ __forceinline__ void upk2(unsigned long long v, float& x, float& y) {
    asm("mov.b64 {%0, %1}, %2;" : "=f"(x), "=f"(y) : "l"(v));
}
__device__ __forceinline__ void ffma2(unsigned long long& d, unsigned long long a,
                                      unsigned long long b) {
    asm("fma.rn.f32x2 %0, %1, %2, %3;" : "=l"(d) : "l"(a), "l"(b), "l"(d));
}

// int64-vs-int32 edge layout probe: int64 (values < 2^31, LE) => odd words zero
__device__ __forceinline__ int detect64(const int* __restrict__ w) {
    int any = 0;
#pragma unroll
    for (int i = 1; i < 128; i += 2) any |= w[i];
    return any == 0;
}

__global__ void k_hist(const int* __restrict__ w) {
    __shared__ int s64;
    if (threadIdx.x == 0) s64 = detect64(w);
    __syncthreads();
    int e = blockIdx.x * blockDim.x + threadIdx.x;
    if (e < EE) {
        int dstv = s64 ? w[2 * (EE + e)] : w[EE + e];
        atomicAdd(&g_deg[dstv], 1);
    }
}

// phase A: per-block scan (+ re-zero g_deg); block totals; local rowptr/cursor
__global__ void k_scanA() {
    __shared__ int wsum[32];
    int tid = threadIdx.x, lane = tid & 31, wid = tid >> 5;
    int i = blockIdx.x * 1024 + tid;
    int v = (i < NN) ? g_deg[i] : 0;
    if (i < NN) g_deg[i] = 0;
    int incl = v;
#pragma unroll
    for (int d = 1; d < 32; d <<= 1) {
        int t = __shfl_up_sync(0xffffffffu, incl, d);
        if (lane >= d) incl += t;
    }
    if (lane == 31) wsum[wid] = incl;
    __syncthreads();
    if (wid == 0) {
        int s = wsum[lane];
        int si = s;
#pragma unroll
        for (int d = 1; d < 32; d <<= 1) {
            int t = __shfl_up_sync(0xffffffffu, si, d);
            if (lane >= d) si += t;
        }
        wsum[lane] = si - s;
        if (lane == 31) g_blk[blockIdx.x] = si;
    }
    __syncthreads();
    if (i < NN) {
        int excl = wsum[wid] + incl - v;
        g_rowptr[i] = excl;
        g_cursor[i] = excl;
        if (i == NN - 1) g_rowptr[NN] = excl + v;   // local total of last block
    }
}

// phase B: scan NB=49 block totals (warp 0) -> g_blkoff; all threads zero g_stats
__global__ void k_scanB() {
    int tid = threadIdx.x;
    g_stats[tid] = 0.f;
    g_stats[256 + tid] = 0.f;
    if (tid < 32) {
        int lane = tid;
        int a = (lane < NB) ? g_blk[lane] : 0;
        int b = (lane + 32 < NB) ? g_blk[lane + 32] : 0;
        int sa = a, sb = b;
#pragma unroll
        for (int d = 1; d < 32; d <<= 1) {
            int t = __shfl_up_sync(0xffffffffu, sa, d);
            if (lane >= d) sa += t;
            int u = __shfl_up_sync(0xffffffffu, sb, d);
            if (lane >= d) sb += u;
        }
        int T1 = __shfl_sync(0xffffffffu, sa, 31);
        if (lane < NB) g_blkoff[lane] = sa - a;
        if (lane + 32 < NB) g_blkoff[lane + 32] = T1 + sb - b;
    }
}

__global__ void k_scatter(const int* __restrict__ w) {
    __shared__ int s64;
    if (threadIdx.x == 0) s64 = detect64(w);
    __syncthreads();
    int e = blockIdx.x * blockDim.x + threadIdx.x;
    if (e < EE) {
        int srcv = s64 ? w[2 * e] : w[e];
        int dstv = s64 ? w[2 * (EE + e)] : w[EE + e];
        int p = atomicAdd(&g_cursor[dstv], 1) + g_blkoff[dstv >> 10];
        g_colidx[p] = srcv;
    }
}

// FUSED: softmax aggregation (warp-per-node, 8 nodes/warp) directly into smem A-tile,
// then GEMM1: g_h1[tile,128] = (aggr + x) @ W1 + b1, with BN partial stats.
// smem: As[64 rows][64 ch] = 16384B + Bs[64][128] = 32768B -> 49152B exactly.
__global__ void k_ag1(const float* __restrict__ x_in, const float* __restrict__ tp,
                      int layer, const float* __restrict__ W,
                      const float* __restrict__ bias) {
    extern __shared__ float sm[];
    float* As = sm;               // [64][64] node-major
    float* Bs = sm + 64 * 64;     // [64][128]
    int tid = threadIdx.x;
    int lane = tid & 31, wid = tid >> 5;
    int m0 = blockIdx.x * 64;
    const float* xp = (layer == 0) ? x_in : g_xbuf;
    float t = __ldg(&tp[layer]);

    // stage W while aggregation's gathers are in flight
    for (int i = tid; i < 64 * 32; i += 256)
        ((float4*)Bs)[i] = ((const float4*)W)[i];

    const float2* x2 = (const float2*)xp;
#pragma unroll 1
    for (int n = 0; n < 8; n++) {
        int gw = m0 + wid * 8 + n;
        if (gw < NN) {
            int beg = g_rowptr[gw] + g_blkoff[gw >> 10];
            int end = g_rowptr[gw + 1] + g_blkoff[(gw + 1) >> 10];
            float den0 = 0.f, den1 = 0.f, num0 = 0.f, num1 = 0.f;
            int i = beg;
            int s = (i < end) ? g_colidx[i] : 0;
            for (; i < end; i++) {
                int snext = (i + 1 < end) ? g_colidx[i + 1] : 0;
                float2 xv = x2[(size_t)s * 32 + lane];
                float m0v = fmaxf(xv.x, 0.f) + GEPS;
                float m1v = fmaxf(xv.y, 0.f) + GEPS;
                float e0 = __expf(m0v * t);
                float e1 = __expf(m1v * t);
                den0 += e0; num0 += m0v * e0;
                den1 += e1; num1 += m1v * e1;
                s = snext;
            }
            float2 xv = x2[(size_t)gw * 32 + lane];
            float2 o;
            o.x = num0 / (den0 + 1e-16f) + xv.x;
            o.y = num1 / (den1 + 1e-16f) + xv.y;
            *(float2*)(As + (wid * 8 + n) * 64 + 2 * lane) = o;
        }
    }
    __syncthreads();

    int tx = tid & 15, ty = tid >> 4;
    unsigned long long acc[4][4];
#pragma unroll
    for (int r = 0; r < 4; r++)
#pragma unroll
        for (int p = 0; p < 4; p++) acc[r][p] = 0ull;

#pragma unroll 8
    for (int k = 0; k < 64; k++) {
        unsigned long long ar[4];
#pragma unroll
        for (int r = 0; r < 4; r++) {
            float a = As[(ty * 4 + r) * 64 + k];
            ar[r] = pk2(a, a);
        }
#pragma unroll
        for (int p = 0; p < 4; p++) {
            unsigned long long bv =
                *(const unsigned long long*)(Bs + k * CH2 + tx * 2 + p * 32);
#pragma unroll
            for (int r = 0; r < 4; r++) ffma2(acc[r][p], ar[r], bv);
        }
    }
    __syncthreads();   // done reading Bs; reuse as reduction scratch

    float bb[8], ps[8], pq[8];
#pragma unroll
    for (int p = 0; p < 4; p++) {
        int col = tx * 2 + p * 32;
        bb[2 * p] = __ldg(&bias[col]); bb[2 * p + 1] = __ldg(&bias[col + 1]);
        ps[2 * p] = ps[2 * p + 1] = 0.f;
        pq[2 * p] = pq[2 * p + 1] = 0.f;
    }
#pragma unroll
    for (int r = 0; r < 4; r++) {
        int row = m0 + ty * 4 + r;
        if (row < NN) {
#pragma unroll
            for (int p = 0; p < 4; p++) {
                float v0, v1;
                upk2(acc[r][p], v0, v1);
                v0 += bb[2 * p]; v1 += bb[2 * p + 1];
                int col = tx * 2 + p * 32;
                *(float2*)(g_h1 + (size_t)row * CH2 + col) = make_float2(v0, v1);
                ps[2 * p] += v0; pq[2 * p] += v0 * v0;
                ps[2 * p + 1] += v1; pq[2 * p + 1] += v1 * v1;
            }
        }
    }
    float* red = Bs;
#pragma unroll
    for (int p = 0; p < 4; p++) {
        int col = tx * 2 + p * 32;
        red[ty * CH2 + col] = ps[2 * p];
        red[ty * CH2 + col + 1] = ps[2 * p + 1];
        red[2048 + ty * CH2 + col] = pq[2 * p];
        red[2048 + ty * CH2 + col + 1] = pq[2 * p + 1];
    }
    __syncthreads();
    if (tid < CH2) {
        float s1 = 0.f, s2 = 0.f;
#pragma unroll
        for (int j = 0; j < 16; j++) { s1 += red[j * CH2 + tid]; s2 += red[2048 + j * CH2 + tid]; }
        float* st = g_stats + layer * 2 * CH2;
        atomicAdd(&st[tid], s1);
        atomicAdd(&st[CH2 + tid], s2);
    }
}

// GEMM2: out[NN,64] = relu( relu(BN(g_h1)) @ W[128,64] + b )
// 64-row tile, two k-passes. smem: As[64][128]=32768B + Bs[64][64]=16384B = 49152B.
__global__ void k_gemm2(const float* __restrict__ W, const float* __restrict__ bias,
                        const float* __restrict__ gamma, const float* __restrict__ beta,
                        int layer, float* __restrict__ Oout, int to_out) {
    extern __shared__ float sm[];
    float* As = sm;                // [64 rows][128 ch]
    float* Bs = sm + 64 * CH2;     // [64 k][64 cols]
    int tid = threadIdx.x;
    int m0 = blockIdx.x * 64;
    float* O = to_out ? Oout : g_xbuf;
    const float* st = g_stats + layer * 2 * CH2;

    // fill A row-major with BN+ReLU; BN affine derived inline from stats
    const float inv = 1.f / (float)NN;
    for (int i = tid; i < 64 * 32; i += 256) {
        int r = i >> 5, cg = i & 31;
        int c = cg * 4;
        float4 v = make_float4(0.f, 0.f, 0.f, 0.f);
        if (m0 + r < NN) v = *(const float4*)(g_h1 + (size_t)(m0 + r) * CH2 + c);
        float4 s1 = *(const float4*)(st + c);
        float4 s2 = *(const float4*)(st + CH2 + c);
        float4 gg = *(const float4*)(gamma + c);
        float4 bb = *(const float4*)(beta + c);
        float m, sc;
        float4 o;
        m = s1.x * inv; sc = gg.x * rsqrtf(s2.x * inv - m * m + BNEPS);
        o.x = fmaxf(fmaf(v.x, sc, bb.x - m * sc), 0.f);
        m = s1.y * inv; sc = gg.y * rsqrtf(s2.y * inv - m * m + BNEPS);
        o.y = fmaxf(fmaf(v.y, sc, bb.y - m * sc), 0.f);
        m = s1.z * inv; sc = gg.z * rsqrtf(s2.z * inv - m * m + BNEPS);
        o.z = fmaxf(fmaf(v.z, sc, bb.z - m * sc), 0.f);
        m = s1.w * inv; sc = gg.w * rsqrtf(s2.w * inv - m * m + BNEPS);
        o.w = fmaxf(fmaf(v.w, sc, bb.w - m * sc), 0.f);
        *(float4*)(As + r * CH2 + c) = o;
    }

    int tx = tid & 15, ty = tid >> 4;
    unsigned long long acc[4][2];
#pragma unroll
    for (int r = 0; r < 4; r++) { acc[r][0] = 0ull; acc[r][1] = 0ull; }

#pragma unroll 1
    for (int h = 0; h < 2; h++) {
        __syncthreads();   // protects Bs reuse across passes (and A fill on h=0)
        for (int i = tid; i < 64 * 16; i += 256)
            ((float4*)Bs)[i] = ((const float4*)W)[h * 64 * 16 + i];
        __syncthreads();
#pragma unroll 8
        for (int kk = 0; kk < 64; kk++) {
            int k = h * 64 + kk;
            unsigned long long ar[4];
#pragma unroll
            for (int r = 0; r < 4; r++) {
                float a = As[(ty * 4 + r) * CH2 + k];
                ar[r] = pk2(a, a);
            }
            unsigned long long b0 = *(const unsigned long long*)(Bs + kk * CC + tx * 2);
            unsigned long long b1 = *(const unsigned long long*)(Bs + kk * CC + tx * 2 + 32);
#pragma unroll
            for (int r = 0; r < 4; r++) {
                ffma2(acc[r][0], ar[r], b0);
                ffma2(acc[r][1], ar[r], b1);
            }
        }
    }
#pragma unroll
    for (int r = 0; r < 4; r++) {
        int row = m0 + ty * 4 + r;
        if (row < NN) {
#pragma unroll
            for (int p = 0; p < 2; p++) {
                int col = tx * 2 + p * 32;
                float v0, v1;
                upk2(acc[r][p], v0, v1);
                v0 = fmaxf(v0 + __ldg(&bias[col]), 0.f);
                v1 = fmaxf(v1 + __ldg(&bias[col + 1]), 0.f);
                *(float2*)(O + (size_t)row * CC + col) = make_float2(v0, v1);
            }
        }
    }
}

extern "C" void kernel_launch(void* const* d_in, const int* in_sizes, int n_in,
                              void* d_out, int out_size) {
    const float* x  = (const float*)d_in[0];
    const int*   ei = (const int*)d_in[1];     // int32 or int64 (auto-detected)
    const float* W1 = (const float*)d_in[2];
    const float* b1 = (const float*)d_in[3];
    const float* gm = (const float*)d_in[4];
    const float* bt = (const float*)d_in[5];
    const float* W2 = (const float*)d_in[6];
    const float* b2 = (const float*)d_in[7];
    const float* tt = (const float*)d_in[8];
    float* out = (float*)d_out;

    const int smem1 = (64 * 64 + 64 * 128) * 4;     // 49152 B
    const int smem2 = (64 * 128 + 64 * 64) * 4;     // 49152 B

    // CSR build (recomputed every call; edge_index is an input)
    k_hist<<<(EE + 255) / 256, 256>>>(ei);
    k_scanA<<<NB, 1024>>>();
    k_scanB<<<1, 256>>>();
    k_scatter<<<(EE + 255) / 256, 256>>>(ei);

    for (int l = 0; l < 2; l++) {
        k_ag1<<<(NN + 63) / 64, 256, smem1>>>(x, tt, l, W1 + (size_t)l * CC * CH2,
                                              b1 + l * CH2);
        k_gemm2<<<(NN + 63) / 64, 256, smem2>>>(W2 + (size_t)l * CH2 * CC, b2 + l * CC,
                                                gm + l * CH2, bt + l * CH2, l, out, l == 1);
    }
}